// round 13
// baseline (speedup 1.0000x reference)
#include <cuda_runtime.h>
#include <math.h>

#define MAXN 100000
#define MAXE 1600000
#define HDIM 64
#define SCAN_B 1024

// Scratch (__device__ globals; no allocation allowed)
__device__ __align__(256) float g_hs[(size_t)MAXN * HDIM];   // layer GEMM output
__device__ __align__(256) float g_buf[(size_t)MAXN * HDIM];  // layer output / next input
__device__ float g_dinv[MAXN];
__device__ int g_cnt[MAXN];        // in-degree histogram
__device__ int g_rowptr[MAXN + 1]; // CSR row offsets (by dst)
__device__ int g_cursor[MAXN];     // fill cursors
__device__ int2 g_cedge[MAXE];     // CSR entries: (src, bits(dinv[src]))
__device__ int g_btotal[128];      // per-block totals (+1 sentinel) for decoupled scan

// packed f32x2 ops (B300)
#define FMA2(d, a, b, c) \
    asm("fma.rn.f32x2 %0, %1, %2, %3;" : "=l"(d) : "l"(a), "l"(b), "l"(c))
#define ADD2(d, a, b) \
    asm("add.rn.f32x2 %0, %1, %2;" : "=l"(d) : "l"(a), "l"(b))
#define PACK2(d, f) \
    asm("mov.b64 %0, {%1, %1};" : "=l"(d) : "f"(f))

// ---------------- CSR build (R8 shapes) ----------------
__global__ void hist_kernel(const int* __restrict__ dst, int E) {
    int i = blockIdx.x * blockDim.x + threadIdx.x;
    if (i < E) atomicAdd(&g_cnt[dst[i]], 1);
}

// Single-launch scan: 98 blocks, fully wave-1 resident -> lookback deadlock-free
__global__ __launch_bounds__(SCAN_B) void scan_fused_kernel(int n, int E) {
    __shared__ int wsum[32];
    __shared__ int s_prefix;
    int bid = blockIdx.x;
    int i = bid * SCAN_B + threadIdx.x;
    int lane = threadIdx.x & 31, w = threadIdx.x >> 5;
    int v = (i < n) ? g_cnt[i] : 0;
    int x = v;
#pragma unroll
    for (int off = 1; off < 32; off <<= 1) {
        int t = __shfl_up_sync(0xffffffffu, x, off);
        if (lane >= off) x += t;
    }
    if (lane == 31) wsum[w] = x;
    __syncthreads();
    if (w == 0) {
        int s = wsum[lane];
#pragma unroll
        for (int off = 1; off < 32; off <<= 1) {
            int t = __shfl_up_sync(0xffffffffu, s, off);
            if (lane >= off) s += t;
        }
        wsum[lane] = s;
    }
    __syncthreads();
    int incl = x + (w > 0 ? wsum[w - 1] : 0);

    if (threadIdx.x == 0) {
        s_prefix = 0;
        atomicExch(&g_btotal[bid], wsum[31] + 1);  // sentinel +1 (0 == not ready)
    }
    __syncthreads();
    if (threadIdx.x < bid) {
        int t;
        do { t = atomicAdd(&g_btotal[threadIdx.x], 0); } while (t == 0);
        atomicAdd_block(&s_prefix, t - 1);
    }
    __syncthreads();
    int prefix = s_prefix;

    if (i < n) {
        int r = prefix + incl - v;
        g_rowptr[i] = r;
        g_cursor[i] = r;
        g_dinv[i] = rsqrtf((float)v + 1.0f);
    }
    if (i == 0) g_rowptr[n] = E;
}

__global__ void fill_kernel(const int* __restrict__ src, const int* __restrict__ dst, int E) {
    int i = blockIdx.x * blockDim.x + threadIdx.x;
    if (i < E) {
        int d = dst[i], s = src[i];
        int pos = atomicAdd(&g_cursor[d], 1);
        g_cedge[pos] = make_int2(s, __float_as_int(g_dinv[s]));
    }
}

// ---------------- GEMM (R9 best shape: 256 thr / 64 rows) ----------------
template <int K, bool SCALE>
__global__ __launch_bounds__(256) void gemm_kernel(const float* __restrict__ Xin,
                                                   const float* __restrict__ W, int n) {
    constexpr int KP = K + 4;
    extern __shared__ float smem[];
    float* sWt = smem;            // [64][KP] transposed W
    float* sX  = smem + 64 * KP;  // [64][K]

    const float* X = Xin ? Xin : g_buf;
    int tid = threadIdx.x;

    for (int i = tid; i < K * 64; i += 256) {
        int k = i >> 6, c = i & 63;
        sWt[c * KP + k] = W[i];
    }
    int row0 = blockIdx.x * 64;
    int nrows = n - row0; if (nrows > 64) nrows = 64;
    for (int i = tid; i < nrows * K; i += 256) sX[i] = X[(size_t)row0 * K + i];
    __syncthreads();

    int w = tid >> 5, lane = tid & 31;
    unsigned long long acc0[8], acc1[8];  // (even-k, odd-k) packed partial sums
#pragma unroll
    for (int r = 0; r < 8; r++) { acc0[r] = 0ull; acc1[r] = 0ull; }

    const ulonglong2* wt0 = (const ulonglong2*)(sWt + lane * KP);
    const ulonglong2* wt1 = (const ulonglong2*)(sWt + (lane + 32) * KP);
#pragma unroll 4
    for (int k4 = 0; k4 < K / 4; k4++) {
        ulonglong2 w0 = wt0[k4];
        ulonglong2 w1 = wt1[k4];
#pragma unroll
        for (int r = 0; r < 8; r++) {
            ulonglong2 xv = ((const ulonglong2*)(sX + (w * 8 + r) * K))[k4];
            FMA2(acc0[r], w0.x, xv.x, acc0[r]);
            FMA2(acc0[r], w0.y, xv.y, acc0[r]);
            FMA2(acc1[r], w1.x, xv.x, acc1[r]);
            FMA2(acc1[r], w1.y, xv.y, acc1[r]);
        }
    }

#pragma unroll
    for (int r = 0; r < 8; r++) {
        int row = row0 + w * 8 + r;
        if (row < n) {
            float sc = SCALE ? g_dinv[row] : 1.0f;
            float e0, o0, e1, o1;
            asm("mov.b64 {%0, %1}, %2;" : "=f"(e0), "=f"(o0) : "l"(acc0[r]));
            asm("mov.b64 {%0, %1}, %2;" : "=f"(e1), "=f"(o1) : "l"(acc1[r]));
            size_t o = (size_t)row * HDIM;
            g_hs[o + lane]      = (e0 + o0) * sc;
            g_hs[o + lane + 32] = (e1 + o1) * sc;
        }
    }
}

// ---------------- fused aggregate + LN + GELU (+ head) ----------------
// warp per node; lane covers cols {2*lane, 2*lane+1}; SSRC: apply dinv[src] per edge
template <bool SSRC>
__global__ __launch_bounds__(256) void agg_post_kernel(const float* __restrict__ b,
                                                       const float* __restrict__ g,
                                                       const float* __restrict__ be, int n, int last,
                                                       const float* __restrict__ Wh,
                                                       const float* __restrict__ bh,
                                                       float* __restrict__ out) {
    int w = threadIdx.x >> 5, lane = threadIdx.x & 31;
    int row = blockIdx.x * 8 + w;
    if (row >= n) return;

    const unsigned long long* hs2 = (const unsigned long long*)g_hs;
    size_t ro = (size_t)row * 32 + lane;
    unsigned long long self = hs2[ro];
    float dv = g_dinv[row];

    unsigned long long aE = 0ull, aO = 0ull;
    if (SSRC) {
        unsigned long long dvp; PACK2(dvp, dv);
        FMA2(aE, self, dvp, aE);     // h[row]*dv
    } else {
        ADD2(aE, aE, self);          // hs[row] already scaled
    }

    int beg = g_rowptr[row], end = g_rowptr[row + 1];
    for (int base = beg; base < end; base += 32) {
        int e = base + lane;
        int2 ev = (e < end) ? __ldg(&g_cedge[e]) : make_int2(0, 0);
        int cnt = end - base; if (cnt > 32) cnt = 32;
        int j = 0;
        for (; j + 2 <= cnt; j += 2) {
            int s0 = __shfl_sync(0xffffffffu, ev.x, j);
            int s1 = __shfl_sync(0xffffffffu, ev.x, j + 1);
            unsigned long long v0 = __ldg(hs2 + (size_t)s0 * 32 + lane);
            unsigned long long v1 = __ldg(hs2 + (size_t)s1 * 32 + lane);
            if (SSRC) {
                float f0 = __int_as_float(__shfl_sync(0xffffffffu, ev.y, j));
                float f1 = __int_as_float(__shfl_sync(0xffffffffu, ev.y, j + 1));
                unsigned long long p0, p1;
                PACK2(p0, f0); PACK2(p1, f1);
                FMA2(aE, v0, p0, aE);
                FMA2(aO, v1, p1, aO);
            } else {
                ADD2(aE, aE, v0);
                ADD2(aO, aO, v1);
            }
        }
        if (j < cnt) {
            int s0 = __shfl_sync(0xffffffffu, ev.x, j);
            unsigned long long v0 = __ldg(hs2 + (size_t)s0 * 32 + lane);
            if (SSRC) {
                float f0 = __int_as_float(__shfl_sync(0xffffffffu, ev.y, j));
                unsigned long long p0; PACK2(p0, f0);
                FMA2(aE, v0, p0, aE);
            } else {
                ADD2(aE, aE, v0);
            }
        }
    }

    unsigned long long at;
    ADD2(at, aE, aO);
    float a0, a1;
    asm("mov.b64 {%0, %1}, %2;" : "=f"(a0), "=f"(a1) : "l"(at));

    float2 bb = ((const float2*)b)[lane];
    float v0 = a0 * dv + bb.x;
    float v1 = a1 * dv + bb.y;

    float s = v0 + v1;
#pragma unroll
    for (int off = 16; off; off >>= 1) s += __shfl_xor_sync(0xffffffffu, s, off);
    float m = s * (1.0f / 64.0f);
    float d0 = v0 - m, d1 = v1 - m;
    float vv = d0 * d0 + d1 * d1;
#pragma unroll
    for (int off = 16; off; off >>= 1) vv += __shfl_xor_sync(0xffffffffu, vv, off);
    float rs = rsqrtf(vv * (1.0f / 64.0f) + 1e-5f);

    float2 gg = ((const float2*)g)[lane];
    float2 ee = ((const float2*)be)[lane];
    float y0 = d0 * rs * gg.x + ee.x;
    float y1 = d1 * rs * gg.y + ee.y;
    y0 = 0.5f * y0 * (1.0f + erff(y0 * 0.70710678118654752f));
    y1 = 0.5f * y1 * (1.0f + erff(y1 * 0.70710678118654752f));

    if (!last) {
        float2 yy; yy.x = y0; yy.y = y1;
        ((float2*)g_buf)[ro] = yy;
    } else {
        float2 wh = ((const float2*)Wh)[lane];
        float hsum = y0 * wh.x + y1 * wh.y;
#pragma unroll
        for (int off = 16; off; off >>= 1) hsum += __shfl_xor_sync(0xffffffffu, hsum, off);
        if (lane == 0) out[row] = hsum + bh[0];
    }
}

extern "C" void kernel_launch(void* const* d_in, const int* in_sizes, int n_in,
                              void* d_out, int out_size) {
    const float* x   = (const float*)d_in[0];
    const int*   ei  = (const int*)d_in[1];
    const float* W1  = (const float*)d_in[2];
    const float* b1  = (const float*)d_in[3];
    const float* g1  = (const float*)d_in[4];
    const float* be1 = (const float*)d_in[5];
    const float* W2  = (const float*)d_in[6];
    const float* b2  = (const float*)d_in[7];
    const float* g2  = (const float*)d_in[8];
    const float* be2 = (const float*)d_in[9];
    const float* W3  = (const float*)d_in[10];
    const float* b3  = (const float*)d_in[11];
    const float* g3  = (const float*)d_in[12];
    const float* be3 = (const float*)d_in[13];
    const float* Wh  = (const float*)d_in[14];
    const float* bh  = (const float*)d_in[15];
    float* out = (float*)d_out;

    int N = in_sizes[0] / 128;
    int E = in_sizes[1] / 2;
    const int* src = ei;
    const int* dst = ei + E;

    size_t sh128 = (size_t)(64 * 132 + 64 * 128) * sizeof(float);  // 66560 B
    size_t sh64  = (size_t)(64 * 68 + 64 * 64) * sizeof(float);    // 33792 B
    cudaFuncSetAttribute(gemm_kernel<128, false>, cudaFuncAttributeMaxDynamicSharedMemorySize, (int)sh128);
    cudaFuncSetAttribute(gemm_kernel<64, true>,   cudaFuncAttributeMaxDynamicSharedMemorySize, (int)sh64);

    int nscan = (N + SCAN_B - 1) / SCAN_B;  // 98 <= 128, wave-1 resident
    int gblocks = (N + 63) / 64;
    int ablocks = (N + 7) / 8;

    void* cnt_ptr = nullptr; void* btot_ptr = nullptr;
    cudaGetSymbolAddress(&cnt_ptr, g_cnt);
    cudaGetSymbolAddress(&btot_ptr, g_btotal);

    // Fork: CSR build chain on side stream, gemm1 (dinv-independent) on main.
    // Created per call, never destroyed (kernel_launch runs only a handful of
    // times; streams/events hold no tracked device memory).
    cudaStream_t s2; cudaStreamCreateWithFlags(&s2, cudaStreamNonBlocking);
    cudaEvent_t evF, evJ;
    cudaEventCreateWithFlags(&evF, cudaEventDisableTiming);
    cudaEventCreateWithFlags(&evJ, cudaEventDisableTiming);

    cudaEventRecord(evF, 0);
    cudaStreamWaitEvent(s2, evF, 0);
    cudaMemsetAsync(cnt_ptr, 0, (size_t)N * sizeof(int), s2);
    cudaMemsetAsync(btot_ptr, 0, 128 * sizeof(int), s2);
    hist_kernel<<<(E + 255) / 256, 256, 0, s2>>>(dst, E);
    scan_fused_kernel<<<nscan, SCAN_B, 0, s2>>>(N, E);
    fill_kernel<<<(E + 255) / 256, 256, 0, s2>>>(src, dst, E);
    cudaEventRecord(evJ, s2);

    // main stream: layer-1 GEMM (unscaled h), concurrent with CSR build
    gemm_kernel<128, false><<<gblocks, 256, sh128>>>(x, W1, N);

    // join, then the rest of the pipeline on the main stream
    cudaStreamWaitEvent(0, evJ, 0);
    agg_post_kernel<true><<<ablocks, 256>>>(b1, g1, be1, N, 0, nullptr, nullptr, nullptr);

    gemm_kernel<64, true><<<gblocks, 256, sh64>>>(nullptr, W2, N);
    agg_post_kernel<false><<<ablocks, 256>>>(b2, g2, be2, N, 0, nullptr, nullptr, nullptr);

    gemm_kernel<64, true><<<gblocks, 256, sh64>>>(nullptr, W3, N);
    agg_post_kernel<false><<<ablocks, 256>>>(b3, g3, be3, N, 1, Wh, bh, out);
}

// round 14
// speedup vs baseline: 1.7233x; 1.7233x over previous
#include <cuda_runtime.h>
#include <math.h>

#define MAXN 100000
#define MAXE 1600000
#define HDIM 64
#define SCAN_B 1024

// Scratch (__device__ globals; no allocation allowed)
__device__ __align__(256) float g_hs[(size_t)MAXN * HDIM];   // (x@W)*dinv
__device__ __align__(256) float g_buf[(size_t)MAXN * HDIM];  // layer output / next input
__device__ float g_dinv[MAXN];
__device__ int g_cnt[MAXN];        // in-degree histogram
__device__ int g_rowptr[MAXN + 1]; // CSR row offsets (by dst)
__device__ int g_cursor[MAXN];     // fill cursors
__device__ int g_csrc[MAXE];       // CSR src indices
__device__ int g_btotal[128];      // per-block totals (+1 sentinel) for decoupled scan

// packed f32x2 ops (B300)
#define ADD2(d, a, b) \
    asm("add.rn.f32x2 %0, %1, %2;" : "=l"(d) : "l"(a), "l"(b))
#define CVT_TF32(d, f) \
    asm("cvt.rna.tf32.f32 %0, %1;" : "=r"(d) : "f"(f))

// ---------------- CSR build (R8-proven shapes, serial) ----------------
__global__ void hist_kernel(const int* __restrict__ dst, int E) {
    int i = blockIdx.x * blockDim.x + threadIdx.x;
    if (i < E) atomicAdd(&g_cnt[dst[i]], 1);
}

// Single-launch scan: 98 blocks, fully wave-1 resident -> lookback deadlock-free
__global__ __launch_bounds__(SCAN_B) void scan_fused_kernel(int n, int E) {
    __shared__ int wsum[32];
    __shared__ int s_prefix;
    int bid = blockIdx.x;
    int i = bid * SCAN_B + threadIdx.x;
    int lane = threadIdx.x & 31, w = threadIdx.x >> 5;
    int v = (i < n) ? g_cnt[i] : 0;
    int x = v;
#pragma unroll
    for (int off = 1; off < 32; off <<= 1) {
        int t = __shfl_up_sync(0xffffffffu, x, off);
        if (lane >= off) x += t;
    }
    if (lane == 31) wsum[w] = x;
    __syncthreads();
    if (w == 0) {
        int s = wsum[lane];
#pragma unroll
        for (int off = 1; off < 32; off <<= 1) {
            int t = __shfl_up_sync(0xffffffffu, s, off);
            if (lane >= off) s += t;
        }
        wsum[lane] = s;
    }
    __syncthreads();
    int incl = x + (w > 0 ? wsum[w - 1] : 0);

    if (threadIdx.x == 0) {
        s_prefix = 0;
        atomicExch(&g_btotal[bid], wsum[31] + 1);  // sentinel +1 (0 == not ready)
    }
    __syncthreads();
    if (threadIdx.x < bid) {
        int t;
        do { t = atomicAdd(&g_btotal[threadIdx.x], 0); } while (t == 0);
        atomicAdd_block(&s_prefix, t - 1);
    }
    __syncthreads();
    int prefix = s_prefix;

    if (i < n) {
        int r = prefix + incl - v;
        g_rowptr[i] = r;
        g_cursor[i] = r;
        g_dinv[i] = rsqrtf((float)v + 1.0f);
    }
    if (i == 0) g_rowptr[n] = E;
}

__global__ void fill_kernel(const int* __restrict__ src, const int* __restrict__ dst, int E) {
    int i = blockIdx.x * blockDim.x + threadIdx.x;
    if (i < E) {
        int pos = atomicAdd(&g_cursor[dst[i]], 1);
        g_csrc[pos] = src[i];
    }
}

// ---------------- GEMM via tf32 mma.sync: hs = (X @ W) * dinv ----------------
// 128 threads / 4 warps; 128 rows/block; warp = 32 rows (2 m16 tiles) x 64 cols.
// X smem stride K+4 (a-frag conflict-free), W smem stride 72 (b-frag conflict-free).
template <int K>
__global__ __launch_bounds__(128) void gemm_mma_kernel(const float* __restrict__ Xin,
                                                       const float* __restrict__ W, int n) {
    constexpr int XS = K + 4;   // X row stride (floats)
    constexpr int WS = 72;      // W row stride (floats)
    extern __shared__ float smem[];
    float* sW = smem;               // [K][WS]   tf32 bits
    float* sX = smem + K * WS;      // [128][XS] tf32 bits
    const unsigned* sWu = (const unsigned*)sW;
    const unsigned* sXu = (const unsigned*)sX;

    const float* X = Xin ? Xin : g_buf;
    int tid = threadIdx.x;
    int row0 = blockIdx.x * 128;

    // stage W [K][64] -> tf32
    for (int i = tid * 4; i < K * 64; i += 128 * 4) {
        int r = i >> 6, c = i & 63;
        float4 v = *(const float4*)(W + i);
        unsigned t0, t1, t2, t3;
        CVT_TF32(t0, v.x); CVT_TF32(t1, v.y); CVT_TF32(t2, v.z); CVT_TF32(t3, v.w);
        unsigned* p = (unsigned*)(sW + r * WS + c);
        p[0] = t0; p[1] = t1; p[2] = t2; p[3] = t3;
    }
    // stage X rows [row0, row0+128) -> tf32 (zero-pad OOB rows)
    for (int i = tid * 4; i < 128 * K; i += 128 * 4) {
        int r = i / K, c = i % K;
        float4 v = make_float4(0.f, 0.f, 0.f, 0.f);
        if (row0 + r < n) v = *(const float4*)(X + (size_t)(row0 + r) * K + c);
        unsigned t0, t1, t2, t3;
        CVT_TF32(t0, v.x); CVT_TF32(t1, v.y); CVT_TF32(t2, v.z); CVT_TF32(t3, v.w);
        unsigned* p = (unsigned*)(sX + r * XS + c);
        p[0] = t0; p[1] = t1; p[2] = t2; p[3] = t3;
    }
    __syncthreads();

    int wid = tid >> 5, lane = tid & 31;
    int grp = lane >> 2, tig = lane & 3;

    float acc[2][8][4];
#pragma unroll
    for (int mt = 0; mt < 2; mt++)
#pragma unroll
        for (int j = 0; j < 8; j++)
#pragma unroll
            for (int q = 0; q < 4; q++) acc[mt][j][q] = 0.0f;

    int abase0 = (wid * 32 + grp) * XS + tig;        // mt=0 row grp
    int abase1 = (wid * 32 + 16 + grp) * XS + tig;   // mt=1

#pragma unroll
    for (int kk = 0; kk < K / 8; kk++) {
        int k0 = kk * 8;
        unsigned a[2][4];
        a[0][0] = sXu[abase0 + k0];
        a[0][1] = sXu[abase0 + 8 * XS + k0];
        a[0][2] = sXu[abase0 + k0 + 4];
        a[0][3] = sXu[abase0 + 8 * XS + k0 + 4];
        a[1][0] = sXu[abase1 + k0];
        a[1][1] = sXu[abase1 + 8 * XS + k0];
        a[1][2] = sXu[abase1 + k0 + 4];
        a[1][3] = sXu[abase1 + 8 * XS + k0 + 4];
#pragma unroll
        for (int j = 0; j < 8; j++) {
            unsigned b0 = sWu[(k0 + tig) * WS + j * 8 + grp];
            unsigned b1 = sWu[(k0 + tig + 4) * WS + j * 8 + grp];
#pragma unroll
            for (int mt = 0; mt < 2; mt++) {
                asm("mma.sync.aligned.m16n8k8.row.col.f32.tf32.tf32.f32 "
                    "{%0,%1,%2,%3}, {%4,%5,%6,%7}, {%8,%9}, {%0,%1,%2,%3};"
                    : "+f"(acc[mt][j][0]), "+f"(acc[mt][j][1]),
                      "+f"(acc[mt][j][2]), "+f"(acc[mt][j][3])
                    : "r"(a[mt][0]), "r"(a[mt][1]), "r"(a[mt][2]), "r"(a[mt][3]),
                      "r"(b0), "r"(b1));
            }
        }
    }

    // epilogue: scale by dinv[row], store float2 (cols j*8+2tig, +1)
#pragma unroll
    for (int mt = 0; mt < 2; mt++) {
        int rA = row0 + wid * 32 + mt * 16 + grp;
        int rB = rA + 8;
        float dA = (rA < n) ? g_dinv[rA] : 0.0f;
        float dB = (rB < n) ? g_dinv[rB] : 0.0f;
#pragma unroll
        for (int j = 0; j < 8; j++) {
            int c = j * 8 + 2 * tig;
            if (rA < n) {
                float2 v; v.x = acc[mt][j][0] * dA; v.y = acc[mt][j][1] * dA;
                *(float2*)(g_hs + (size_t)rA * HDIM + c) = v;
            }
            if (rB < n) {
                float2 v; v.x = acc[mt][j][2] * dB; v.y = acc[mt][j][3] * dB;
                *(float2*)(g_hs + (size_t)rB * HDIM + c) = v;
            }
        }
    }
}

// ---------------- fused aggregate + LN + GELU (+ head) ----------------
// warp per node; lane covers cols {2*lane, 2*lane+1} via LDG.64 + packed adds
__global__ __launch_bounds__(256) void agg_post_kernel(const float* __restrict__ b,
                                                       const float* __restrict__ g,
                                                       const float* __restrict__ be, int n, int last,
                                                       const float* __restrict__ Wh,
                                                       const float* __restrict__ bh,
                                                       float* __restrict__ out) {
    int w = threadIdx.x >> 5, lane = threadIdx.x & 31;
    int row = blockIdx.x * 8 + w;
    if (row >= n) return;

    const unsigned long long* hs2 = (const unsigned long long*)g_hs;
    size_t ro = (size_t)row * 32 + lane;
    unsigned long long aE = hs2[ro];  // self-loop term (hs already dinv-scaled)
    unsigned long long aO = 0ull;

    int beg = g_rowptr[row], end = g_rowptr[row + 1];
    for (int base = beg; base < end; base += 32) {
        int e = base + lane;
        int s = (e < end) ? g_csrc[e] : 0;
        int cnt = end - base; if (cnt > 32) cnt = 32;
        int j = 0;
        for (; j + 2 <= cnt; j += 2) {
            int s0 = __shfl_sync(0xffffffffu, s, j);
            int s1 = __shfl_sync(0xffffffffu, s, j + 1);
            unsigned long long v0 = __ldg(hs2 + (size_t)s0 * 32 + lane);
            unsigned long long v1 = __ldg(hs2 + (size_t)s1 * 32 + lane);
            ADD2(aE, aE, v0);
            ADD2(aO, aO, v1);
        }
        if (j < cnt) {
            int s0 = __shfl_sync(0xffffffffu, s, j);
            unsigned long long v0 = __ldg(hs2 + (size_t)s0 * 32 + lane);
            ADD2(aE, aE, v0);
        }
    }

    unsigned long long at;
    ADD2(at, aE, aO);
    float a0, a1;
    asm("mov.b64 {%0, %1}, %2;" : "=f"(a0), "=f"(a1) : "l"(at));

    float dv = g_dinv[row];
    float2 bb = ((const float2*)b)[lane];
    float v0 = a0 * dv + bb.x;
    float v1 = a1 * dv + bb.y;

    float s = v0 + v1;
#pragma unroll
    for (int off = 16; off; off >>= 1) s += __shfl_xor_sync(0xffffffffu, s, off);
    float m = s * (1.0f / 64.0f);
    float d0 = v0 - m, d1 = v1 - m;
    float vv = d0 * d0 + d1 * d1;
#pragma unroll
    for (int off = 16; off; off >>= 1) vv += __shfl_xor_sync(0xffffffffu, vv, off);
    float rs = rsqrtf(vv * (1.0f / 64.0f) + 1e-5f);

    float2 gg = ((const float2*)g)[lane];
    float2 ee = ((const float2*)be)[lane];
    float y0 = d0 * rs * gg.x + ee.x;
    float y1 = d1 * rs * gg.y + ee.y;
    y0 = 0.5f * y0 * (1.0f + erff(y0 * 0.70710678118654752f));
    y1 = 0.5f * y1 * (1.0f + erff(y1 * 0.70710678118654752f));

    if (!last) {
        float2 yy; yy.x = y0; yy.y = y1;
        ((float2*)g_buf)[ro] = yy;
    } else {
        float2 wh = ((const float2*)Wh)[lane];
        float hsum = y0 * wh.x + y1 * wh.y;
#pragma unroll
        for (int off = 16; off; off >>= 1) hsum += __shfl_xor_sync(0xffffffffu, hsum, off);
        if (lane == 0) out[row] = hsum + bh[0];
    }
}

extern "C" void kernel_launch(void* const* d_in, const int* in_sizes, int n_in,
                              void* d_out, int out_size) {
    const float* x   = (const float*)d_in[0];
    const int*   ei  = (const int*)d_in[1];
    const float* W1  = (const float*)d_in[2];
    const float* b1  = (const float*)d_in[3];
    const float* g1  = (const float*)d_in[4];
    const float* be1 = (const float*)d_in[5];
    const float* W2  = (const float*)d_in[6];
    const float* b2  = (const float*)d_in[7];
    const float* g2  = (const float*)d_in[8];
    const float* be2 = (const float*)d_in[9];
    const float* W3  = (const float*)d_in[10];
    const float* b3  = (const float*)d_in[11];
    const float* g3  = (const float*)d_in[12];
    const float* be3 = (const float*)d_in[13];
    const float* Wh  = (const float*)d_in[14];
    const float* bh  = (const float*)d_in[15];
    float* out = (float*)d_out;

    int N = in_sizes[0] / 128;
    int E = in_sizes[1] / 2;
    const int* src = ei;
    const int* dst = ei + E;

    size_t sh128 = (size_t)(128 * 72 + 128 * 132) * sizeof(float);  // 104448 B
    size_t sh64  = (size_t)(64 * 72 + 128 * 68) * sizeof(float);    // 53248 B
    cudaFuncSetAttribute(gemm_mma_kernel<128>, cudaFuncAttributeMaxDynamicSharedMemorySize, (int)sh128);
    cudaFuncSetAttribute(gemm_mma_kernel<64>,  cudaFuncAttributeMaxDynamicSharedMemorySize, (int)sh64);

    int nscan = (N + SCAN_B - 1) / SCAN_B;  // 98 <= 128, wave-1 resident
    int gblocks = (N + 127) / 128;
    int ablocks = (N + 7) / 8;

    void* cnt_ptr = nullptr; void* btot_ptr = nullptr;
    cudaGetSymbolAddress(&cnt_ptr, g_cnt);
    cudaGetSymbolAddress(&btot_ptr, g_btotal);
    cudaMemsetAsync(cnt_ptr, 0, (size_t)N * sizeof(int));
    cudaMemsetAsync(btot_ptr, 0, 128 * sizeof(int));
    hist_kernel<<<(E + 255) / 256, 256>>>(dst, E);
    scan_fused_kernel<<<nscan, SCAN_B>>>(N, E);
    fill_kernel<<<(E + 255) / 256, 256>>>(src, dst, E);

    // layer 1 (K=128)
    gemm_mma_kernel<128><<<gblocks, 128, sh128>>>(x, W1, N);
    agg_post_kernel<<<ablocks, 256>>>(b1, g1, be1, N, 0, nullptr, nullptr, nullptr);

    // layer 2 (K=64)
    gemm_mma_kernel<64><<<gblocks, 128, sh64>>>(nullptr, W2, N);
    agg_post_kernel<<<ablocks, 256>>>(b2, g2, be2, N, 0, nullptr, nullptr, nullptr);

    // layer 3 (K=64) + fused head
    gemm_mma_kernel<64><<<gblocks, 128, sh64>>>(nullptr, W3, N);
    agg_post_kernel<<<ablocks, 256>>>(b3, g3, be3, N, 1, Wh, bh, out);
}

// round 15
// speedup vs baseline: 1.7798x; 1.0328x over previous
#include <cuda_runtime.h>
#include <math.h>

#define MAXN 100000
#define MAXE 1600000
#define HDIM 64
#define SCAN_B 1024

// Scratch (__device__ globals; no allocation allowed)
__device__ __align__(256) float g_hs[(size_t)MAXN * HDIM];   // (x@W)*dinv
__device__ __align__(256) float g_buf[(size_t)MAXN * HDIM];  // layer output / next input
__device__ float g_dinv[MAXN];
__device__ int g_cnt[MAXN];        // in-degree histogram
__device__ int g_rowptr[MAXN + 1]; // CSR row offsets (by dst)
__device__ int g_cursor[MAXN];     // fill cursors
__device__ int g_csrc[MAXE];       // CSR src indices
__device__ int g_btotal[128];      // per-block totals (+1 sentinel) for decoupled scan

// packed f32x2 ops (B300)
#define ADD2(d, a, b) \
    asm("add.rn.f32x2 %0, %1, %2;" : "=l"(d) : "l"(a), "l"(b))
#define CVT_TF32(d, f) \
    asm("cvt.rna.tf32.f32 %0, %1;" : "=r"(d) : "f"(f))

// ---------------- CSR build (R8-proven shapes, serial) ----------------
__global__ void hist_kernel(const int* __restrict__ dst, int E) {
    int i = blockIdx.x * blockDim.x + threadIdx.x;
    if (i < E) atomicAdd(&g_cnt[dst[i]], 1);
}

// Single-launch scan: 98 blocks, fully wave-1 resident -> lookback deadlock-free
__global__ __launch_bounds__(SCAN_B) void scan_fused_kernel(int n, int E) {
    __shared__ int wsum[32];
    __shared__ int s_prefix;
    int bid = blockIdx.x;
    int i = bid * SCAN_B + threadIdx.x;
    int lane = threadIdx.x & 31, w = threadIdx.x >> 5;
    int v = (i < n) ? g_cnt[i] : 0;
    int x = v;
#pragma unroll
    for (int off = 1; off < 32; off <<= 1) {
        int t = __shfl_up_sync(0xffffffffu, x, off);
        if (lane >= off) x += t;
    }
    if (lane == 31) wsum[w] = x;
    __syncthreads();
    if (w == 0) {
        int s = wsum[lane];
#pragma unroll
        for (int off = 1; off < 32; off <<= 1) {
            int t = __shfl_up_sync(0xffffffffu, s, off);
            if (lane >= off) s += t;
        }
        wsum[lane] = s;
    }
    __syncthreads();
    int incl = x + (w > 0 ? wsum[w - 1] : 0);

    if (threadIdx.x == 0) {
        s_prefix = 0;
        atomicExch(&g_btotal[bid], wsum[31] + 1);  // sentinel +1 (0 == not ready)
    }
    __syncthreads();
    if (threadIdx.x < bid) {
        int t;
        do { t = atomicAdd(&g_btotal[threadIdx.x], 0); } while (t == 0);
        atomicAdd_block(&s_prefix, t - 1);
    }
    __syncthreads();
    int prefix = s_prefix;

    if (i < n) {
        int r = prefix + incl - v;
        g_rowptr[i] = r;
        g_cursor[i] = r;
        g_dinv[i] = rsqrtf((float)v + 1.0f);
    }
    if (i == 0) g_rowptr[n] = E;
}

__global__ void fill_kernel(const int* __restrict__ src, const int* __restrict__ dst, int E) {
    int i = blockIdx.x * blockDim.x + threadIdx.x;
    if (i < E) {
        int pos = atomicAdd(&g_cursor[dst[i]], 1);
        g_csrc[pos] = src[i];
    }
}

// ---------------- GEMM via tf32 mma.sync: hs = (X @ W) * dinv ----------------
// 256 threads / 8 warps; 128 rows/block; warp = one m16 tile (16 rows) x 64 cols.
// X smem stride K+4 (a-frag conflict-free), W smem stride 72 (b-frag conflict-free).
template <int K>
__global__ __launch_bounds__(256) void gemm_mma_kernel(const float* __restrict__ Xin,
                                                       const float* __restrict__ W, int n) {
    constexpr int XS = K + 4;   // X row stride (floats)
    constexpr int WS = 72;      // W row stride (floats)
    extern __shared__ float smem[];
    float* sW = smem;               // [K][WS]   tf32 bits
    float* sX = smem + K * WS;      // [128][XS] tf32 bits
    const unsigned* sWu = (const unsigned*)sW;
    const unsigned* sXu = (const unsigned*)sX;

    const float* X = Xin ? Xin : g_buf;
    int tid = threadIdx.x;
    int row0 = blockIdx.x * 128;

    // stage W [K][64] -> tf32
    for (int i = tid * 4; i < K * 64; i += 256 * 4) {
        int r = i >> 6, c = i & 63;
        float4 v = *(const float4*)(W + i);
        unsigned t0, t1, t2, t3;
        CVT_TF32(t0, v.x); CVT_TF32(t1, v.y); CVT_TF32(t2, v.z); CVT_TF32(t3, v.w);
        unsigned* p = (unsigned*)(sW + r * WS + c);
        p[0] = t0; p[1] = t1; p[2] = t2; p[3] = t3;
    }
    // stage X rows [row0, row0+128) -> tf32 (zero-pad OOB rows)
    for (int i = tid * 4; i < 128 * K; i += 256 * 4) {
        int r = i / K, c = i % K;
        float4 v = make_float4(0.f, 0.f, 0.f, 0.f);
        if (row0 + r < n) v = *(const float4*)(X + (size_t)(row0 + r) * K + c);
        unsigned t0, t1, t2, t3;
        CVT_TF32(t0, v.x); CVT_TF32(t1, v.y); CVT_TF32(t2, v.z); CVT_TF32(t3, v.w);
        unsigned* p = (unsigned*)(sX + r * XS + c);
        p[0] = t0; p[1] = t1; p[2] = t2; p[3] = t3;
    }
    __syncthreads();

    int wid = tid >> 5, lane = tid & 31;
    int grp = lane >> 2, tig = lane & 3;

    float acc[8][4];
#pragma unroll
    for (int j = 0; j < 8; j++)
#pragma unroll
        for (int q = 0; q < 4; q++) acc[j][q] = 0.0f;

    int abase = (wid * 16 + grp) * XS + tig;

#pragma unroll
    for (int kk = 0; kk < K / 8; kk++) {
        int k0 = kk * 8;
        unsigned a0 = sXu[abase + k0];
        unsigned a1 = sXu[abase + 8 * XS + k0];
        unsigned a2 = sXu[abase + k0 + 4];
        unsigned a3 = sXu[abase + 8 * XS + k0 + 4];
#pragma unroll
        for (int j = 0; j < 8; j++) {
            unsigned b0 = sWu[(k0 + tig) * WS + j * 8 + grp];
            unsigned b1 = sWu[(k0 + tig + 4) * WS + j * 8 + grp];
            asm("mma.sync.aligned.m16n8k8.row.col.f32.tf32.tf32.f32 "
                "{%0,%1,%2,%3}, {%4,%5,%6,%7}, {%8,%9}, {%0,%1,%2,%3};"
                : "+f"(acc[j][0]), "+f"(acc[j][1]), "+f"(acc[j][2]), "+f"(acc[j][3])
                : "r"(a0), "r"(a1), "r"(a2), "r"(a3), "r"(b0), "r"(b1));
        }
    }

    // epilogue: scale by dinv[row], store float2 (cols j*8+2tig, +1)
    int rA = row0 + wid * 16 + grp;
    int rB = rA + 8;
    float dA = (rA < n) ? g_dinv[rA] : 0.0f;
    float dB = (rB < n) ? g_dinv[rB] : 0.0f;
#pragma unroll
    for (int j = 0; j < 8; j++) {
        int c = j * 8 + 2 * tig;
        if (rA < n) {
            float2 v; v.x = acc[j][0] * dA; v.y = acc[j][1] * dA;
            *(float2*)(g_hs + (size_t)rA * HDIM + c) = v;
        }
        if (rB < n) {
            float2 v; v.x = acc[j][2] * dB; v.y = acc[j][3] * dB;
            *(float2*)(g_hs + (size_t)rB * HDIM + c) = v;
        }
    }
}

// ---------------- fused aggregate + LN + GELU (+ head) ----------------
// warp per node; lane covers cols {2*lane, 2*lane+1} via LDG.64 + packed adds
__global__ __launch_bounds__(256) void agg_post_kernel(const float* __restrict__ b,
                                                       const float* __restrict__ g,
                                                       const float* __restrict__ be, int n, int last,
                                                       const float* __restrict__ Wh,
                                                       const float* __restrict__ bh,
                                                       float* __restrict__ out) {
    int w = threadIdx.x >> 5, lane = threadIdx.x & 31;
    int row = blockIdx.x * 8 + w;
    if (row >= n) return;

    const unsigned long long* hs2 = (const unsigned long long*)g_hs;
    size_t ro = (size_t)row * 32 + lane;
    unsigned long long aE = hs2[ro];  // self-loop term (hs already dinv-scaled)
    unsigned long long aO = 0ull;

    int beg = g_rowptr[row], end = g_rowptr[row + 1];
    for (int base = beg; base < end; base += 32) {
        int e = base + lane;
        int s = (e < end) ? g_csrc[e] : 0;
        int cnt = end - base; if (cnt > 32) cnt = 32;
        int j = 0;
        for (; j + 2 <= cnt; j += 2) {
            int s0 = __shfl_sync(0xffffffffu, s, j);
            int s1 = __shfl_sync(0xffffffffu, s, j + 1);
            unsigned long long v0 = __ldg(hs2 + (size_t)s0 * 32 + lane);
            unsigned long long v1 = __ldg(hs2 + (size_t)s1 * 32 + lane);
            ADD2(aE, aE, v0);
            ADD2(aO, aO, v1);
        }
        if (j < cnt) {
            int s0 = __shfl_sync(0xffffffffu, s, j);
            unsigned long long v0 = __ldg(hs2 + (size_t)s0 * 32 + lane);
            ADD2(aE, aE, v0);
        }
    }

    unsigned long long at;
    ADD2(at, aE, aO);
    float a0, a1;
    asm("mov.b64 {%0, %1}, %2;" : "=f"(a0), "=f"(a1) : "l"(at));

    float dv = g_dinv[row];
    float2 bb = ((const float2*)b)[lane];
    float v0 = a0 * dv + bb.x;
    float v1 = a1 * dv + bb.y;

    float s = v0 + v1;
#pragma unroll
    for (int off = 16; off; off >>= 1) s += __shfl_xor_sync(0xffffffffu, s, off);
    float m = s * (1.0f / 64.0f);
    float d0 = v0 - m, d1 = v1 - m;
    float vv = d0 * d0 + d1 * d1;
#pragma unroll
    for (int off = 16; off; off >>= 1) vv += __shfl_xor_sync(0xffffffffu, vv, off);
    float rs = rsqrtf(vv * (1.0f / 64.0f) + 1e-5f);

    float2 gg = ((const float2*)g)[lane];
    float2 ee = ((const float2*)be)[lane];
    float y0 = d0 * rs * gg.x + ee.x;
    float y1 = d1 * rs * gg.y + ee.y;
    y0 = 0.5f * y0 * (1.0f + erff(y0 * 0.70710678118654752f));
    y1 = 0.5f * y1 * (1.0f + erff(y1 * 0.70710678118654752f));

    if (!last) {
        float2 yy; yy.x = y0; yy.y = y1;
        ((float2*)g_buf)[ro] = yy;
    } else {
        float2 wh = ((const float2*)Wh)[lane];
        float hsum = y0 * wh.x + y1 * wh.y;
#pragma unroll
        for (int off = 16; off; off >>= 1) hsum += __shfl_xor_sync(0xffffffffu, hsum, off);
        if (lane == 0) out[row] = hsum + bh[0];
    }
}

extern "C" void kernel_launch(void* const* d_in, const int* in_sizes, int n_in,
                              void* d_out, int out_size) {
    const float* x   = (const float*)d_in[0];
    const int*   ei  = (const int*)d_in[1];
    const float* W1  = (const float*)d_in[2];
    const float* b1  = (const float*)d_in[3];
    const float* g1  = (const float*)d_in[4];
    const float* be1 = (const float*)d_in[5];
    const float* W2  = (const float*)d_in[6];
    const float* b2  = (const float*)d_in[7];
    const float* g2  = (const float*)d_in[8];
    const float* be2 = (const float*)d_in[9];
    const float* W3  = (const float*)d_in[10];
    const float* b3  = (const float*)d_in[11];
    const float* g3  = (const float*)d_in[12];
    const float* be3 = (const float*)d_in[13];
    const float* Wh  = (const float*)d_in[14];
    const float* bh  = (const float*)d_in[15];
    float* out = (float*)d_out;

    int N = in_sizes[0] / 128;
    int E = in_sizes[1] / 2;
    const int* src = ei;
    const int* dst = ei + E;

    size_t sh128 = (size_t)(128 * 72 + 128 * 132) * sizeof(float);  // 104448 B
    size_t sh64  = (size_t)(64 * 72 + 128 * 68) * sizeof(float);    // 53248 B
    cudaFuncSetAttribute(gemm_mma_kernel<128>, cudaFuncAttributeMaxDynamicSharedMemorySize, (int)sh128);
    cudaFuncSetAttribute(gemm_mma_kernel<64>,  cudaFuncAttributeMaxDynamicSharedMemorySize, (int)sh64);

    int nscan = (N + SCAN_B - 1) / SCAN_B;  // 98 <= 128, wave-1 resident
    int gblocks = (N + 127) / 128;
    int ablocks = (N + 7) / 8;

    void* cnt_ptr = nullptr; void* btot_ptr = nullptr;
    cudaGetSymbolAddress(&cnt_ptr, g_cnt);
    cudaGetSymbolAddress(&btot_ptr, g_btotal);
    cudaMemsetAsync(cnt_ptr, 0, (size_t)N * sizeof(int));
    cudaMemsetAsync(btot_ptr, 0, 128 * sizeof(int));
    hist_kernel<<<(E + 255) / 256, 256>>>(dst, E);
    scan_fused_kernel<<<nscan, SCAN_B>>>(N, E);
    fill_kernel<<<(E + 255) / 256, 256>>>(src, dst, E);

    // layer 1 (K=128)
    gemm_mma_kernel<128><<<gblocks, 256, sh128>>>(x, W1, N);
    agg_post_kernel<<<ablocks, 256>>>(b1, g1, be1, N, 0, nullptr, nullptr, nullptr);

    // layer 2 (K=64)
    gemm_mma_kernel<64><<<gblocks, 256, sh64>>>(nullptr, W2, N);
    agg_post_kernel<<<ablocks, 256>>>(b2, g2, be2, N, 0, nullptr, nullptr, nullptr);

    // layer 3 (K=64) + fused head
    gemm_mma_kernel<64><<<gblocks, 256, sh64>>>(nullptr, W3, N);
    agg_post_kernel<<<ablocks, 256>>>(b3, g3, be3, N, 1, Wh, bh, out);
}

// round 16
// speedup vs baseline: 1.9735x; 1.1089x over previous
#include <cuda_runtime.h>
#include <math.h>

#define MAXN 100000
#define MAXE 1600000
#define HDIM 64
#define SCAN_B 1024

// Scratch (__device__ globals; no allocation allowed)
__device__ __align__(256) float g_hs[(size_t)MAXN * HDIM];   // (x@W)*dinv
__device__ __align__(256) float g_buf[(size_t)MAXN * HDIM];  // layer output / next input
__device__ float g_dinv[MAXN];
__device__ int g_cnt[MAXN];
__device__ int g_rowptr[MAXN + 1];
__device__ int g_cursor[MAXN];
__device__ int g_csrc[MAXE];
__device__ int g_btotal[128];

#define ADD2(d, a, b) \
    asm("add.rn.f32x2 %0, %1, %2;" : "=l"(d) : "l"(a), "l"(b))
#define CVT_TF32(d, f) \
    asm("cvt.rna.tf32.f32 %0, %1;" : "=r"(d) : "f"(f))
#define CP_ASYNC16(sa, gp) \
    asm volatile("cp.async.cg.shared.global [%0], [%1], 16;" :: "r"(sa), "l"(gp))
#define CP_COMMIT() asm volatile("cp.async.commit_group;")
#define CP_WAIT(N)  asm volatile("cp.async.wait_group %0;" :: "n"(N))

// ---------------- CSR build (serial, R8-proven) ----------------
__global__ void hist_kernel(const int* __restrict__ dst, int E) {
    int i = blockIdx.x * blockDim.x + threadIdx.x;
    if (i < E) atomicAdd(&g_cnt[dst[i]], 1);
}

__global__ __launch_bounds__(SCAN_B) void scan_fused_kernel(int n, int E) {
    __shared__ int wsum[32];
    __shared__ int s_prefix;
    int bid = blockIdx.x;
    int i = bid * SCAN_B + threadIdx.x;
    int lane = threadIdx.x & 31, w = threadIdx.x >> 5;
    int v = (i < n) ? g_cnt[i] : 0;
    int x = v;
#pragma unroll
    for (int off = 1; off < 32; off <<= 1) {
        int t = __shfl_up_sync(0xffffffffu, x, off);
        if (lane >= off) x += t;
    }
    if (lane == 31) wsum[w] = x;
    __syncthreads();
    if (w == 0) {
        int s = wsum[lane];
#pragma unroll
        for (int off = 1; off < 32; off <<= 1) {
            int t = __shfl_up_sync(0xffffffffu, s, off);
            if (lane >= off) s += t;
        }
        wsum[lane] = s;
    }
    __syncthreads();
    int incl = x + (w > 0 ? wsum[w - 1] : 0);

    if (threadIdx.x == 0) {
        s_prefix = 0;
        atomicExch(&g_btotal[bid], wsum[31] + 1);
    }
    __syncthreads();
    if (threadIdx.x < bid) {
        int t;
        do { t = atomicAdd(&g_btotal[threadIdx.x], 0); } while (t == 0);
        atomicAdd_block(&s_prefix, t - 1);
    }
    __syncthreads();
    int prefix = s_prefix;

    if (i < n) {
        int r = prefix + incl - v;
        g_rowptr[i] = r;
        g_cursor[i] = r;
        g_dinv[i] = rsqrtf((float)v + 1.0f);
    }
    if (i == 0) g_rowptr[n] = E;
}

__global__ void fill_kernel(const int* __restrict__ src, const int* __restrict__ dst, int E) {
    int i = blockIdx.x * blockDim.x + threadIdx.x;
    if (i < E) {
        int pos = atomicAdd(&g_cursor[dst[i]], 1);
        g_csrc[pos] = src[i];
    }
}

// ---------------- persistent tf32-mma GEMM with cp.async double buffer ----------------
// 256 threads / 8 warps. Tile = 64 rows x 64 cols. Warp = 16 rows x 32 cols.
// sW: [K][72] tf32 (converted once). sX: 2 x [64][K+4] raw fp32 (cvt after LDS).
template <int K>
__global__ __launch_bounds__(256) void gemm_mma_pipe(const float* __restrict__ Xin,
                                                     const float* __restrict__ W, int n,
                                                     int tpb) {
    constexpr int XS = K + 4;
    constexpr int WS = 72;
    constexpr int CPR = K / 4;         // 16B chunks per row
    extern __shared__ float smem[];
    float* sW = smem;                  // [K][WS]
    float* sX = smem + K * WS;         // [2][64][XS]
    const unsigned* sWu = (const unsigned*)sW;

    const float* X = Xin ? Xin : g_buf;
    int tid = threadIdx.x;

    // stage W -> tf32 (once per block)
    for (int i = tid * 4; i < K * 64; i += 1024) {
        int r = i >> 6, c = i & 63;
        float4 v = *(const float4*)(W + i);
        unsigned t0, t1, t2, t3;
        CVT_TF32(t0, v.x); CVT_TF32(t1, v.y); CVT_TF32(t2, v.z); CVT_TF32(t3, v.w);
        unsigned* p = (unsigned*)(sW + r * WS + c);
        p[0] = t0; p[1] = t1; p[2] = t2; p[3] = t3;
    }

    int T = (n + 63) / 64;
    int t0 = blockIdx.x * tpb;
    int nt = T - t0; if (nt > tpb) nt = tpb;
    if (nt <= 0) return;

    // async-load one 64-row tile into buffer half bi
    auto load_tile = [&](int tile, int bi) {
        float* dst = sX + bi * 64 * XS;
        int row0 = tile * 64;
        for (int c = tid; c < 64 * CPR; c += 256) {
            int r = c / CPR, c4 = c % CPR;
            int row = row0 + r; if (row >= n) row = 0;  // clamp; garbage rows masked at store
            const float* gp = X + (size_t)row * K + c4 * 4;
            unsigned sa = (unsigned)__cvta_generic_to_shared(dst + r * XS + c4 * 4);
            CP_ASYNC16(sa, gp);
        }
    };

    load_tile(t0, 0);
    CP_COMMIT();

    int wid = tid >> 5, lane = tid & 31;
    int grp = lane >> 2, tig = lane & 3;
    int mrow = (wid & 3) * 16;
    int n0 = (wid >> 2) * 32;

    for (int i = 0; i < nt; i++) {
        if (i + 1 < nt) {
            load_tile(t0 + i + 1, (i + 1) & 1);
            CP_COMMIT();
            CP_WAIT(1);
        } else {
            CP_WAIT(0);
        }
        __syncthreads();   // tile i visible to all (also covers W staging on i==0)

        const float* cur = sX + (i & 1) * 64 * XS;
        float acc[4][4];
#pragma unroll
        for (int j = 0; j < 4; j++)
#pragma unroll
            for (int q = 0; q < 4; q++) acc[j][q] = 0.0f;

#pragma unroll
        for (int kk = 0; kk < K / 8; kk++) {
            int k0 = kk * 8;
            float af0 = cur[(mrow + grp) * XS + k0 + tig];
            float af1 = cur[(mrow + 8 + grp) * XS + k0 + tig];
            float af2 = cur[(mrow + grp) * XS + k0 + tig + 4];
            float af3 = cur[(mrow + 8 + grp) * XS + k0 + tig + 4];
            unsigned a0, a1, a2, a3;
            CVT_TF32(a0, af0); CVT_TF32(a1, af1); CVT_TF32(a2, af2); CVT_TF32(a3, af3);
#pragma unroll
            for (int j = 0; j < 4; j++) {
                unsigned b0 = sWu[(k0 + tig) * WS + n0 + j * 8 + grp];
                unsigned b1 = sWu[(k0 + tig + 4) * WS + n0 + j * 8 + grp];
                asm("mma.sync.aligned.m16n8k8.row.col.f32.tf32.tf32.f32 "
                    "{%0,%1,%2,%3}, {%4,%5,%6,%7}, {%8,%9}, {%0,%1,%2,%3};"
                    : "+f"(acc[j][0]), "+f"(acc[j][1]), "+f"(acc[j][2]), "+f"(acc[j][3])
                    : "r"(a0), "r"(a1), "r"(a2), "r"(a3), "r"(b0), "r"(b1));
            }
        }

        // epilogue: scale by dinv, store
        int row0 = (t0 + i) * 64;
        int rA = row0 + mrow + grp;
        int rB = rA + 8;
        float dA = (rA < n) ? g_dinv[rA] : 0.0f;
        float dB = (rB < n) ? g_dinv[rB] : 0.0f;
#pragma unroll
        for (int j = 0; j < 4; j++) {
            int c = n0 + j * 8 + 2 * tig;
            if (rA < n) {
                float2 v; v.x = acc[j][0] * dA; v.y = acc[j][1] * dA;
                *(float2*)(g_hs + (size_t)rA * HDIM + c) = v;
            }
            if (rB < n) {
                float2 v; v.x = acc[j][2] * dB; v.y = acc[j][3] * dB;
                *(float2*)(g_hs + (size_t)rB * HDIM + c) = v;
            }
        }
        __syncthreads();   // all warps done with buffer (i&1) before it is refilled
    }
}

// ---------------- fused aggregate + LN + GELU (+ head) ----------------
__global__ __launch_bounds__(256) void agg_post_kernel(const float* __restrict__ b,
                                                       const float* __restrict__ g,
                                                       const float* __restrict__ be, int n, int last,
                                                       const float* __restrict__ Wh,
                                                       const float* __restrict__ bh,
                                                       float* __restrict__ out) {
    int w = threadIdx.x >> 5, lane = threadIdx.x & 31;
    int row = blockIdx.x * 8 + w;
    if (row >= n) return;

    const unsigned long long* hs2 = (const unsigned long long*)g_hs;
    size_t ro = (size_t)row * 32 + lane;
    unsigned long long aE = hs2[ro];
    unsigned long long aO = 0ull;

    int beg = g_rowptr[row], end = g_rowptr[row + 1];
    for (int base = beg; base < end; base += 32) {
        int e = base + lane;
        int s = (e < end) ? g_csrc[e] : 0;
        int cnt = end - base; if (cnt > 32) cnt = 32;
        int j = 0;
        for (; j + 2 <= cnt; j += 2) {
            int s0 = __shfl_sync(0xffffffffu, s, j);
            int s1 = __shfl_sync(0xffffffffu, s, j + 1);
            unsigned long long v0 = __ldg(hs2 + (size_t)s0 * 32 + lane);
            unsigned long long v1 = __ldg(hs2 + (size_t)s1 * 32 + lane);
            ADD2(aE, aE, v0);
            ADD2(aO, aO, v1);
        }
        if (j < cnt) {
            int s0 = __shfl_sync(0xffffffffu, s, j);
            unsigned long long v0 = __ldg(hs2 + (size_t)s0 * 32 + lane);
            ADD2(aE, aE, v0);
        }
    }

    unsigned long long at;
    ADD2(at, aE, aO);
    float a0, a1;
    asm("mov.b64 {%0, %1}, %2;" : "=f"(a0), "=f"(a1) : "l"(at));

    float dv = g_dinv[row];
    float2 bb = ((const float2*)b)[lane];
    float v0 = a0 * dv + bb.x;
    float v1 = a1 * dv + bb.y;

    float s = v0 + v1;
#pragma unroll
    for (int off = 16; off; off >>= 1) s += __shfl_xor_sync(0xffffffffu, s, off);
    float m = s * (1.0f / 64.0f);
    float d0 = v0 - m, d1 = v1 - m;
    float vv = d0 * d0 + d1 * d1;
#pragma unroll
    for (int off = 16; off; off >>= 1) vv += __shfl_xor_sync(0xffffffffu, vv, off);
    float rs = rsqrtf(vv * (1.0f / 64.0f) + 1e-5f);

    float2 gg = ((const float2*)g)[lane];
    float2 ee = ((const float2*)be)[lane];
    float y0 = d0 * rs * gg.x + ee.x;
    float y1 = d1 * rs * gg.y + ee.y;
    y0 = 0.5f * y0 * (1.0f + erff(y0 * 0.70710678118654752f));
    y1 = 0.5f * y1 * (1.0f + erff(y1 * 0.70710678118654752f));

    if (!last) {
        float2 yy; yy.x = y0; yy.y = y1;
        ((float2*)g_buf)[ro] = yy;
    } else {
        float2 wh = ((const float2*)Wh)[lane];
        float hsum = y0 * wh.x + y1 * wh.y;
#pragma unroll
        for (int off = 16; off; off >>= 1) hsum += __shfl_xor_sync(0xffffffffu, hsum, off);
        if (lane == 0) out[row] = hsum + bh[0];
    }
}

extern "C" void kernel_launch(void* const* d_in, const int* in_sizes, int n_in,
                              void* d_out, int out_size) {
    const float* x   = (const float*)d_in[0];
    const int*   ei  = (const int*)d_in[1];
    const float* W1  = (const float*)d_in[2];
    const float* b1  = (const float*)d_in[3];
    const float* g1  = (const float*)d_in[4];
    const float* be1 = (const float*)d_in[5];
    const float* W2  = (const float*)d_in[6];
    const float* b2  = (const float*)d_in[7];
    const float* g2  = (const float*)d_in[8];
    const float* be2 = (const float*)d_in[9];
    const float* W3  = (const float*)d_in[10];
    const float* b3  = (const float*)d_in[11];
    const float* g3  = (const float*)d_in[12];
    const float* be3 = (const float*)d_in[13];
    const float* Wh  = (const float*)d_in[14];
    const float* bh  = (const float*)d_in[15];
    float* out = (float*)d_out;

    int N = in_sizes[0] / 128;
    int E = in_sizes[1] / 2;
    const int* src = ei;
    const int* dst = ei + E;

    size_t sh128 = (size_t)(128 * 72 + 2 * 64 * 132) * sizeof(float);  // 104448 B
    size_t sh64  = (size_t)(64 * 72 + 2 * 64 * 68) * sizeof(float);    // 53248 B
    cudaFuncSetAttribute(gemm_mma_pipe<128>, cudaFuncAttributeMaxDynamicSharedMemorySize, (int)sh128);
    cudaFuncSetAttribute(gemm_mma_pipe<64>,  cudaFuncAttributeMaxDynamicSharedMemorySize, (int)sh64);

    int nscan = (N + SCAN_B - 1) / SCAN_B;
    int ablocks = (N + 7) / 8;
    int T = (N + 63) / 64;                 // 64-row tiles
    int G1 = 2 * 148; if (G1 > T) G1 = T;  // 2 blocks/SM (K=128)
    int G2 = 4 * 148; if (G2 > T) G2 = T;  // 4 blocks/SM (K=64)
    int tpb1 = (T + G1 - 1) / G1;
    int tpb2 = (T + G2 - 1) / G2;

    void* cnt_ptr = nullptr; void* btot_ptr = nullptr;
    cudaGetSymbolAddress(&cnt_ptr, g_cnt);
    cudaGetSymbolAddress(&btot_ptr, g_btotal);
    cudaMemsetAsync(cnt_ptr, 0, (size_t)N * sizeof(int));
    cudaMemsetAsync(btot_ptr, 0, 128 * sizeof(int));
    hist_kernel<<<(E + 255) / 256, 256>>>(dst, E);
    scan_fused_kernel<<<nscan, SCAN_B>>>(N, E);
    fill_kernel<<<(E + 255) / 256, 256>>>(src, dst, E);

    // layer 1 (K=128)
    gemm_mma_pipe<128><<<G1, 256, sh128>>>(x, W1, N, tpb1);
    agg_post_kernel<<<ablocks, 256>>>(b1, g1, be1, N, 0, nullptr, nullptr, nullptr);

    // layer 2 (K=64)
    gemm_mma_pipe<64><<<G2, 256, sh64>>>(nullptr, W2, N, tpb2);
    agg_post_kernel<<<ablocks, 256>>>(b2, g2, be2, N, 0, nullptr, nullptr, nullptr);

    // layer 3 (K=64) + fused head
    gemm_mma_pipe<64><<<G2, 256, sh64>>>(nullptr, W3, N, tpb2);
    agg_post_kernel<<<ablocks, 256>>>(b3, g3, be3, N, 1, Wh, bh, out);
}